// round 2
// baseline (speedup 1.0000x reference)
#include <cuda_runtime.h>
#include <math.h>

#define B_TOT   32768
#define T_STEPS 32
#define HID     128
#define GATES   512
#define OBS_OS  8
#define OBS_TS  6
#define SDIM    200     // 8 + 32*6
#define NACT    9
#define M_TILE  32
#define NTHREADS 512
#define NCTA    (B_TOT / M_TILE)

typedef unsigned long long u64;

// ---------------- scratch (no allocations allowed) ----------------
__device__ int g_nobs[B_TOT];
__device__ int g_perm[B_TOT];
__device__ int g_hist[T_STEPS + 1];
__device__ int g_cursor[T_STEPS + 1];

// ---------------- shared-memory layout (float offsets) ----------------
#define O_BUF   0
#define SZ_BUF  (512 * 36)
#define O_SH    (O_BUF + SZ_BUF)          // h:   [m][132]
#define O_SC    (O_SH + 32 * 132)         // c:   [jh][36]
#define O_SHOUT (O_SC + 128 * 36)         // hout:[m][128]
#define O_XCAT  (O_SHOUT + 32 * 128)      // xcat:[m][256]
#define O_C1    (O_XCAT + 32 * 256)       // c1:  [m][132]
#define O_X     (O_C1 + 32 * 132)         // x_t: [m][8]
#define O_X2    (O_X + 32 * 8)            // s_OS:[m][8]
#define O_WC2   (O_X2 + 32 * 8)           // W_c2:[o][132]
#define O_INT   (O_WC2 + 9 * 132)
#define SMEM_FLOATS (O_INT + 64)
#define SMEM_BYTES  (SMEM_FLOATS * 4)

// ---------------- packed f32x2 helpers (FFMA2) ----------------
__device__ __forceinline__ void fma2(u64 &d, u64 a, u64 b) {
    asm("fma.rn.f32x2 %0, %1, %2, %0;" : "+l"(d) : "l"(a), "l"(b));
}
__device__ __forceinline__ u64 pack2(float a, float b) {
    u64 r; asm("mov.b64 %0, {%1, %2};" : "=l"(r) : "f"(a), "f"(b)); return r;
}
__device__ __forceinline__ float hsum2(u64 v) {
    unsigned lo, hi;
    asm("mov.b64 {%0, %1}, %2;" : "=r"(lo), "=r"(hi) : "l"(v));
    return __uint_as_float(lo) + __uint_as_float(hi);
}

__device__ __forceinline__ float sigf(float x) {
    float e = __expf(-x);
    return __fdividef(1.0f, 1.0f + e);
}
__device__ __forceinline__ float tanh_a(float x) {
    return 2.0f * sigf(2.0f * x) - 1.0f;
}

// ---------------- pre-pass: length bucketing ----------------
__global__ void k_zero() {
    int t = threadIdx.x;
    if (t <= T_STEPS) g_hist[t] = 0;
}

__global__ void k_count(const float* __restrict__ s) {
    int m = blockIdx.x * blockDim.x + threadIdx.x;
    if (m >= B_TOT) return;
    const float* p = s + m * SDIM + OBS_OS;
    int cnt = 0;
#pragma unroll
    for (int t = 0; t < T_STEPS; ++t) {
        float v = p[t * OBS_TS];
        cnt += (v == v) ? 1 : 0;   // !isnan
    }
    g_nobs[m] = cnt;
    atomicAdd(&g_hist[cnt], 1);
}

__global__ void k_prefix() {
    int off = 0;
    for (int len = T_STEPS; len >= 0; --len) {
        g_cursor[len] = off;
        off += g_hist[len];
    }
}

__global__ void k_scatter() {
    int m = blockIdx.x * blockDim.x + threadIdx.x;
    if (m >= B_TOT) return;
    int pos = atomicAdd(&g_cursor[g_nobs[m]], 1);
    g_perm[pos] = m;
}

// no-op: aligns k_main to ncu launch index 5 (-s 5 -c 1)
__global__ void k_align() {}

// ---------------- fused main kernel ----------------
__global__ void __launch_bounds__(NTHREADS, 1)
k_main(const float* __restrict__ s,
       const float* __restrict__ W_os, const float* __restrict__ b_os,
       const float* __restrict__ W_ih, const float* __restrict__ W_hh,
       const float* __restrict__ b_ih, const float* __restrict__ b_hh,
       const float* __restrict__ W_ts, const float* __restrict__ b_ts,
       const float* __restrict__ W_c1, const float* __restrict__ b_c1,
       const float* __restrict__ W_c2, const float* __restrict__ b_c2,
       float* __restrict__ out)
{
    extern __shared__ float sm[];
    float* sW    = sm + O_BUF;
    float* sH    = sm + O_SH;
    float* sC    = sm + O_SC;
    float* sHout = sm + O_SHOUT;
    float* sXcat = sm + O_XCAT;
    float* sC1o  = sm + O_C1;
    float* sX    = sm + O_X;
    float* sX2   = sm + O_X2;
    float* sWc2  = sm + O_WC2;
    int*   sNobs = (int*)(sm + O_INT);
    int*   sSamp = sNobs + 32;
    __shared__ int sTmaxS;

    const int tid = threadIdx.x;
    const int j   = tid;          // owned gate row (0..511)
    const int jh  = tid & 127;    // hidden unit
    const int mg  = tid >> 7;     // sample group (0..3)
    const int base = blockIdx.x * M_TILE;

    if (tid < M_TILE) {
        int idx = g_perm[base + tid];
        sSamp[tid] = idx;
        sNobs[tid] = g_nobs[idx];
    }
    for (int i = tid; i < 32 * 132; i += NTHREADS) sH[i] = 0.0f;
    for (int i = tid; i < 128 * 36; i += NTHREADS) sC[i] = 0.0f;
    for (int i = tid; i < 32 * 128; i += NTHREADS) sHout[i] = 0.0f;
    __syncthreads();
    if (tid == 0) {
        int tm = 0;
        for (int m = 0; m < M_TILE; ++m) tm = max(tm, sNobs[m]);
        sTmaxS = tm;
    }

    // per-thread LSTM input weights (packed) + fused bias
    u64 wih01 = pack2(W_ih[j * OBS_TS + 0], W_ih[j * OBS_TS + 1]);
    u64 wih23 = pack2(W_ih[j * OBS_TS + 2], W_ih[j * OBS_TS + 3]);
    u64 wih45 = pack2(W_ih[j * OBS_TS + 4], W_ih[j * OBS_TS + 5]);
    const u64 bias2 = pack2(b_ih[j] + b_hh[j], 0.0f);
    __syncthreads();
    const int tmax = sTmaxS;

    // ================= LSTM recurrence =================
    for (int t = 0; t < tmax; ++t) {
        // stage x_t (NaN -> 0)
        if (tid < M_TILE * OBS_TS) {
            int m = tid / OBS_TS, i = tid - m * OBS_TS;
            float v = s[sSamp[m] * SDIM + OBS_OS + t * OBS_TS + i];
            sX[m * 8 + i] = (v == v) ? v : 0.0f;
        }
        __syncthreads();

        u64 acc2[M_TILE];
#pragma unroll
        for (int m = 0; m < M_TILE; ++m) {
            u64 a = bias2;
            const u64* xp = (const u64*)(sX + m * 8);
            fma2(a, wih01, xp[0]);
            fma2(a, wih23, xp[1]);
            fma2(a, wih45, xp[2]);
            acc2[m] = a;
        }

        // gates += h @ W_hh^T (packed f32x2, K staged in 4 chunks of 32)
#pragma unroll 1
        for (int c = 0; c < 4; ++c) {
            __syncthreads();
            {
                const float4* src = (const float4*)(W_hh + j * HID + c * 32);
                float4* dst = (float4*)(sW + j * 36);
#pragma unroll
                for (int q = 0; q < 8; ++q) dst[q] = src[q];
            }
            __syncthreads();
#pragma unroll 1
            for (int kk = 0; kk < 8; ++kk) {
                ulonglong2 w2 = *(const ulonglong2*)(sW + j * 36 + kk * 4);
                int k = c * 32 + kk * 4;
#pragma unroll
                for (int m = 0; m < M_TILE; ++m) {
                    ulonglong2 h2 = *(const ulonglong2*)(sH + m * 132 + k);  // bcast
                    fma2(acc2[m], w2.x, h2.x);
                    fma2(acc2[m], w2.y, h2.y);
                }
            }
        }
        __syncthreads();
        // exchange preacts: buf reused as sG[j][m] (stride 36)
        {
            float4* dst = (float4*)(sW + j * 36);
#pragma unroll
            for (int q = 0; q < 8; ++q)
                dst[q] = make_float4(hsum2(acc2[q * 4]), hsum2(acc2[q * 4 + 1]),
                                     hsum2(acc2[q * 4 + 2]), hsum2(acc2[q * 4 + 3]));
        }
        __syncthreads();
        // gate nonlinearities + state update
#pragma unroll
        for (int mm = 0; mm < 8; ++mm) {
            int m = mg * 8 + mm;
            float gi = sW[(jh      ) * 36 + m];
            float gf = sW[(jh + 128) * 36 + m];
            float gg = sW[(jh + 256) * 36 + m];
            float go = sW[(jh + 384) * 36 + m];
            float iv = sigf(gi), fv = sigf(gf), gv = tanh_a(gg), ov = sigf(go);
            float cv = fmaf(fv, sC[jh * 36 + m], iv * gv);
            sC[jh * 36 + m] = cv;
            float hv = ov * tanh_a(cv);
            sH[m * 132 + jh] = hv;
            if (t == sNobs[m] - 1) sHout[m * 128 + jh] = hv;
        }
        __syncthreads();
    }

    // ================= head =================
    if (tid < M_TILE * OBS_OS) {
        int m = tid >> 3, i = tid & 7;
        sX2[tid] = s[sSamp[m] * SDIM + i];
    }
    {   // stage W_ts -> buf [jh][132]
        const float4* src = (const float4*)(W_ts + jh * HID + mg * 32);
        float4* dst = (float4*)(sW + jh * 132 + mg * 32);
#pragma unroll
        for (int r = 0; r < 8; ++r) dst[r] = src[r];
    }
    if (tid < NACT * 32) {   // stage W_c2 -> [o][132]
        int o = tid >> 5, kb = (tid & 31) * 4;
        *(float4*)(sWc2 + o * 132 + kb) = *(const float4*)(W_c2 + o * HID + kb);
    }
    __syncthreads();

    // x_OS = relu(s_OS @ W_os^T + b_os) -> xcat[:, 0:128]
    {
        float wos[8];
#pragma unroll
        for (int i = 0; i < 8; ++i) wos[i] = W_os[jh * 8 + i];
        float bos = b_os[jh];
#pragma unroll
        for (int mm = 0; mm < 8; ++mm) {
            int m = mg * 8 + mm;
            float a = bos;
#pragma unroll
            for (int i = 0; i < 8; ++i) a = fmaf(wos[i], sX2[m * 8 + i], a);
            sXcat[m * 256 + jh] = fmaxf(a, 0.0f);
        }
    }
    // x_TS = relu(hout @ W_ts^T + b_ts) -> xcat[:, 128:256]  (packed)
    {
        u64 a8[8];
#pragma unroll
        for (int mm = 0; mm < 8; ++mm) a8[mm] = pack2(0.0f, 0.0f);
#pragma unroll 1
        for (int k4 = 0; k4 < 32; ++k4) {
            ulonglong2 w2 = *(const ulonglong2*)(sW + jh * 132 + k4 * 4);
#pragma unroll
            for (int mm = 0; mm < 8; ++mm) {
                int m = mg * 8 + mm;
                ulonglong2 h2 = *(const ulonglong2*)(sHout + m * 128 + k4 * 4);
                fma2(a8[mm], w2.x, h2.x);
                fma2(a8[mm], w2.y, h2.y);
            }
        }
        float bts = b_ts[jh];
#pragma unroll
        for (int mm = 0; mm < 8; ++mm) {
            int m = mg * 8 + mm;
            sXcat[m * 256 + HID + jh] = fmaxf(hsum2(a8[mm]) + bts, 0.0f);
        }
    }
    __syncthreads();

    // c1 = relu(xcat @ W_c1^T + b_c1), K=256 in two staged halves (packed)
    {
        u64 a8[8];
#pragma unroll
        for (int mm = 0; mm < 8; ++mm) a8[mm] = pack2(0.0f, 0.0f);
#pragma unroll 1
        for (int half = 0; half < 2; ++half) {
            __syncthreads();
            {
                const float4* src = (const float4*)(W_c1 + jh * 256 + half * 128 + mg * 32);
                float4* dst = (float4*)(sW + jh * 132 + mg * 32);
#pragma unroll
                for (int r = 0; r < 8; ++r) dst[r] = src[r];
            }
            __syncthreads();
#pragma unroll 1
            for (int k4 = 0; k4 < 32; ++k4) {
                ulonglong2 w2 = *(const ulonglong2*)(sW + jh * 132 + k4 * 4);
#pragma unroll
                for (int mm = 0; mm < 8; ++mm) {
                    int m = mg * 8 + mm;
                    ulonglong2 x2 = *(const ulonglong2*)(sXcat + m * 256 + half * 128 + k4 * 4);
                    fma2(a8[mm], w2.x, x2.x);
                    fma2(a8[mm], w2.y, x2.y);
                }
            }
        }
        float bc1 = b_c1[jh];
#pragma unroll
        for (int mm = 0; mm < 8; ++mm) {
            int m = mg * 8 + mm;
            sC1o[m * 132 + jh] = fmaxf(hsum2(a8[mm]) + bc1, 0.0f);
        }
    }
    __syncthreads();

    // out = c1 @ W_c2^T + b_c2  (9 outputs/sample)
    if (tid < M_TILE * NACT) {
        int m = tid / NACT, o = tid - m * NACT;
        float a = b_c2[o];
#pragma unroll 1
        for (int k4 = 0; k4 < 32; ++k4) {
            float4 w = *(const float4*)(sWc2 + o * 132 + k4 * 4);
            float4 x = *(const float4*)(sC1o + m * 132 + k4 * 4);
            a = fmaf(w.x, x.x, a);
            a = fmaf(w.y, x.y, a);
            a = fmaf(w.z, x.z, a);
            a = fmaf(w.w, x.w, a);
        }
        out[sSamp[m] * NACT + o] = a;
    }
}

// ---------------- launch ----------------
extern "C" void kernel_launch(void* const* d_in, const int* in_sizes, int n_in,
                              void* d_out, int out_size) {
    const float* s    = (const float*)d_in[0];
    const float* W_os = (const float*)d_in[1];
    const float* b_os = (const float*)d_in[2];
    const float* W_ih = (const float*)d_in[3];
    const float* W_hh = (const float*)d_in[4];
    const float* b_ih = (const float*)d_in[5];
    const float* b_hh = (const float*)d_in[6];
    const float* W_ts = (const float*)d_in[7];
    const float* b_ts = (const float*)d_in[8];
    const float* W_c1 = (const float*)d_in[9];
    const float* b_c1 = (const float*)d_in[10];
    const float* W_c2 = (const float*)d_in[11];
    const float* b_c2 = (const float*)d_in[12];
    float* out = (float*)d_out;

    cudaFuncSetAttribute(k_main, cudaFuncAttributeMaxDynamicSharedMemorySize, SMEM_BYTES);

    k_zero<<<1, 64>>>();                       // launch 0
    k_count<<<B_TOT / 256, 256>>>(s);          // launch 1
    k_prefix<<<1, 1>>>();                      // launch 2
    k_scatter<<<B_TOT / 256, 256>>>();         // launch 3
    k_align<<<1, 32>>>();                      // launch 4 (ncu alignment)
    k_main<<<NCTA, NTHREADS, SMEM_BYTES>>>(s, W_os, b_os, W_ih, W_hh, b_ih, b_hh,
                                           W_ts, b_ts, W_c1, b_c1, W_c2, b_c2, out);
}

// round 3
// speedup vs baseline: 1.2271x; 1.2271x over previous
#include <cuda_runtime.h>
#include <math.h>

#define B_TOT   32768
#define T_STEPS 32
#define HID     128
#define GATES   512
#define OBS_OS  8
#define OBS_TS  6
#define SDIM    200     // 8 + 32*6
#define NACT    9
#define M_TILE  64
#define NTHREADS 512
#define NCTA    (B_TOT / M_TILE)

// ---------------- scratch (no allocations allowed) ----------------
__device__ int g_nobs[B_TOT];
__device__ int g_perm[B_TOT];
__device__ int g_hist[T_STEPS + 1];
__device__ int g_cursor[T_STEPS + 1];

// ---------------- shared-memory layout (float offsets) ----------------
// LSTM phase:
//   O_BUF  : W-chunk staging [512][36] (float4-friendly) AND gate exchange [512][33]
//   O_SH   : h [64][132]  (pad -> 16B-aligned float4 broadcast reads)
//   O_SC   : c [128][65]  (odd stride -> conflict-free)
//   O_SHOUT: h snapshot [64][128]
//   O_X    : x_t [64][8]
// Head phase overlays dead LSTM regions:
//   O_XCAT over O_SH/O_SC
#define O_BUF   0
#define O_SH    18432              // 512*36
#define O_SC    26880              // +64*132
#define O_SHOUT 35200              // +128*65
#define O_X     43392              // +64*128
#define O_INT   43904              // +64*8  (ints: nobs[64], samp[64])
#define O_XCAT  O_SH               // 64*256 = 16384 (ends 34816 < 35200)
#define O_C1    44032              // 64*132
#define O_X2    52480              // 64*8
#define O_WC2   52992              // 9*132
#define SMEM_FLOATS 54180
#define SMEM_BYTES  (SMEM_FLOATS * 4)

__device__ __forceinline__ float sigf(float x) {
    float e = __expf(-x);
    return __fdividef(1.0f, 1.0f + e);
}
__device__ __forceinline__ float tanh_a(float x) {
    return 2.0f * sigf(2.0f * x) - 1.0f;
}

// ---------------- pre-pass: length bucketing ----------------
__global__ void k_count(const float* __restrict__ s) {
    int m = blockIdx.x * blockDim.x + threadIdx.x;
    if (m >= B_TOT) return;
    const float* p = s + m * SDIM + OBS_OS;
    int cnt = 0;
#pragma unroll
    for (int t = 0; t < T_STEPS; ++t) {
        float v = p[t * OBS_TS];
        cnt += (v == v) ? 1 : 0;   // !isnan
    }
    g_nobs[m] = cnt;
    atomicAdd(&g_hist[cnt], 1);
}

__global__ void k_prefix() {
    // descending length order; zero hist after reading (leave-clean for next replay;
    // first execution relies on static zero-init of device globals)
    int off = 0;
    for (int len = T_STEPS; len >= 0; --len) {
        g_cursor[len] = off;
        off += g_hist[len];
        g_hist[len] = 0;
    }
}

__global__ void k_scatter() {
    int m = blockIdx.x * blockDim.x + threadIdx.x;
    if (m >= B_TOT) return;
    int pos = atomicAdd(&g_cursor[g_nobs[m]], 1);
    g_perm[pos] = m;
}

// ---------------- fused main kernel ----------------
__global__ void __launch_bounds__(NTHREADS, 1)
k_main(const float* __restrict__ s,
       const float* __restrict__ W_os, const float* __restrict__ b_os,
       const float* __restrict__ W_ih, const float* __restrict__ W_hh,
       const float* __restrict__ b_ih, const float* __restrict__ b_hh,
       const float* __restrict__ W_ts, const float* __restrict__ b_ts,
       const float* __restrict__ W_c1, const float* __restrict__ b_c1,
       const float* __restrict__ W_c2, const float* __restrict__ b_c2,
       float* __restrict__ out)
{
    extern __shared__ float sm[];
    float* sW    = sm + O_BUF;     // staging [j][36]
    float* sH    = sm + O_SH;
    float* sC    = sm + O_SC;
    float* sHout = sm + O_SHOUT;
    float* sX    = sm + O_X;
    float* sXcat = sm + O_XCAT;
    float* sC1o  = sm + O_C1;
    float* sX2   = sm + O_X2;
    float* sWc2  = sm + O_WC2;
    int*   sNobs = (int*)(sm + O_INT);
    int*   sSamp = sNobs + M_TILE;
    __shared__ int sTmaxS;

    const int tid = threadIdx.x;
    const int j   = tid;          // owned gate row (0..511)
    const int jh  = tid & 127;    // hidden unit
    const int mg  = tid >> 7;     // group 0..3
    const int base = blockIdx.x * M_TILE;

    if (tid < M_TILE) {
        int idx = g_perm[base + tid];
        sSamp[tid] = idx;
        sNobs[tid] = g_nobs[idx];
    }
    for (int i = tid; i < M_TILE * 132; i += NTHREADS) sH[i] = 0.0f;
    for (int i = tid; i < 128 * 65;    i += NTHREADS) sC[i] = 0.0f;
    for (int i = tid; i < M_TILE * 128; i += NTHREADS) sHout[i] = 0.0f;
    __syncthreads();
    if (tid == 0) {
        int tm = 0;
        for (int m = 0; m < M_TILE; ++m) tm = max(tm, sNobs[m]);
        sTmaxS = tm;
    }

    // per-thread LSTM input weights + fused bias for owned gate row
    float wih[OBS_TS];
#pragma unroll
    for (int i = 0; i < OBS_TS; ++i) wih[i] = W_ih[j * OBS_TS + i];
    const float bias = b_ih[j] + b_hh[j];
    __syncthreads();
    const int tmax = sTmaxS;

    // ================= LSTM recurrence =================
    for (int t = 0; t < tmax; ++t) {
        // stage x_t (NaN -> 0)
        if (tid < M_TILE * OBS_TS) {
            int m = tid / OBS_TS, i = tid - m * OBS_TS;
            float v = s[sSamp[m] * SDIM + OBS_OS + t * OBS_TS + i];
            sX[m * 8 + i] = (v == v) ? v : 0.0f;
        }
        __syncthreads();

        float acc[M_TILE];
#pragma unroll
        for (int m = 0; m < M_TILE; ++m) {
            float a = bias;
#pragma unroll
            for (int i = 0; i < OBS_TS; ++i) a = fmaf(wih[i], sX[m * 8 + i], a);
            acc[m] = a;
        }

        // gates += h @ W_hh^T, K staged in 4 chunks of 32 (COALESCED load)
#pragma unroll 1
        for (int c = 0; c < 4; ++c) {
            __syncthreads();   // buf free (prev chunk readers / prev-step gates done)
#pragma unroll
            for (int q = 0; q < 8; ++q) {
                int lin = q * NTHREADS + tid;
                int r  = lin >> 3;          // row 0..511
                int cc = lin & 7;           // float4 col in chunk
                *(float4*)(sW + r * 36 + cc * 4) =
                    *(const float4*)(W_hh + r * HID + c * 32 + cc * 4);
            }
            __syncthreads();
#pragma unroll 1
            for (int kk = 0; kk < 8; ++kk) {
                float4 w = *(const float4*)(sW + j * 36 + kk * 4);
                int k = c * 32 + kk * 4;
#pragma unroll
                for (int m = 0; m < M_TILE; ++m) {
                    float4 h = *(const float4*)(sH + m * 132 + k);  // bcast
                    float a = acc[m];
                    a = fmaf(w.x, h.x, a);
                    a = fmaf(w.y, h.y, a);
                    a = fmaf(w.z, h.z, a);
                    a = fmaf(w.w, h.w, a);
                    acc[m] = a;
                }
            }
        }

        // gate exchange + state update in two 32-sample passes
#pragma unroll 1
        for (int p = 0; p < 2; ++p) {
            __syncthreads();   // protect buf (compute readers / prev pass readers)
#pragma unroll
            for (int q = 0; q < 32; ++q)
                sW[j * 33 + q] = acc[p * 32 + q];   // conflict-free (33 odd)
            __syncthreads();
#pragma unroll
            for (int mm = 0; mm < 8; ++mm) {
                int mloc = mg * 8 + mm;            // 0..31 within pass
                int m    = p * 32 + mloc;          // global sample in tile
                float gi = sW[(jh      ) * 33 + mloc];
                float gf = sW[(jh + 128) * 33 + mloc];
                float gg = sW[(jh + 256) * 33 + mloc];
                float go = sW[(jh + 384) * 33 + mloc];
                float iv = sigf(gi), fv = sigf(gf), gv = tanh_a(gg), ov = sigf(go);
                float cv = fmaf(fv, sC[jh * 65 + m], iv * gv);
                sC[jh * 65 + m] = cv;
                float hv = ov * tanh_a(cv);
                sH[m * 132 + jh] = hv;
                if (t == sNobs[m] - 1) sHout[m * 128 + jh] = hv;
            }
        }
        __syncthreads();
    }

    // ================= head =================
    if (tid < M_TILE * OBS_OS) {
        int m = tid >> 3, i = tid & 7;
        sX2[tid] = s[sSamp[m] * SDIM + i];
    }
    {   // stage W_ts -> buf [jh][132]
        const float4* src = (const float4*)(W_ts + jh * HID + mg * 32);
        float4* dst = (float4*)(sW + jh * 132 + mg * 32);
#pragma unroll
        for (int r = 0; r < 8; ++r) dst[r] = src[r];
    }
    if (tid < NACT * 32) {   // stage W_c2 -> [o][132]
        int o = tid >> 5, kb = (tid & 31) * 4;
        *(float4*)(sWc2 + o * 132 + kb) = *(const float4*)(W_c2 + o * HID + kb);
    }
    __syncthreads();

    // x_OS = relu(s_OS @ W_os^T + b_os) -> xcat[:, 0:128]
    {
        float wos[8];
#pragma unroll
        for (int i = 0; i < 8; ++i) wos[i] = W_os[jh * 8 + i];
        float bos = b_os[jh];
#pragma unroll
        for (int mm = 0; mm < 16; ++mm) {
            int m = mg * 16 + mm;
            float a = bos;
#pragma unroll
            for (int i = 0; i < 8; ++i) a = fmaf(wos[i], sX2[m * 8 + i], a);
            sXcat[m * 256 + jh] = fmaxf(a, 0.0f);
        }
    }
    // x_TS = relu(hout @ W_ts^T + b_ts) -> xcat[:, 128:256]
    {
        float a16[16];
#pragma unroll
        for (int mm = 0; mm < 16; ++mm) a16[mm] = 0.0f;
#pragma unroll 1
        for (int k4 = 0; k4 < 32; ++k4) {
            float4 w = *(const float4*)(sW + jh * 132 + k4 * 4);
#pragma unroll
            for (int mm = 0; mm < 16; ++mm) {
                int m = mg * 16 + mm;
                float4 h = *(const float4*)(sHout + m * 128 + k4 * 4);
                float a = a16[mm];
                a = fmaf(w.x, h.x, a);
                a = fmaf(w.y, h.y, a);
                a = fmaf(w.z, h.z, a);
                a = fmaf(w.w, h.w, a);
                a16[mm] = a;
            }
        }
        float bts = b_ts[jh];
#pragma unroll
        for (int mm = 0; mm < 16; ++mm) {
            int m = mg * 16 + mm;
            sXcat[m * 256 + HID + jh] = fmaxf(a16[mm] + bts, 0.0f);
        }
    }
    __syncthreads();

    // c1 = relu(xcat @ W_c1^T + b_c1), K=256 in two staged halves
    {
        float a16[16];
#pragma unroll
        for (int mm = 0; mm < 16; ++mm) a16[mm] = 0.0f;
#pragma unroll 1
        for (int half = 0; half < 2; ++half) {
            __syncthreads();
            {
                const float4* src = (const float4*)(W_c1 + jh * 256 + half * 128 + mg * 32);
                float4* dst = (float4*)(sW + jh * 132 + mg * 32);
#pragma unroll
                for (int r = 0; r < 8; ++r) dst[r] = src[r];
            }
            __syncthreads();
#pragma unroll 1
            for (int k4 = 0; k4 < 32; ++k4) {
                float4 w = *(const float4*)(sW + jh * 132 + k4 * 4);
#pragma unroll
                for (int mm = 0; mm < 16; ++mm) {
                    int m = mg * 16 + mm;
                    float4 x = *(const float4*)(sXcat + m * 256 + half * 128 + k4 * 4);
                    float a = a16[mm];
                    a = fmaf(w.x, x.x, a);
                    a = fmaf(w.y, x.y, a);
                    a = fmaf(w.z, x.z, a);
                    a = fmaf(w.w, x.w, a);
                    a16[mm] = a;
                }
            }
        }
        float bc1 = b_c1[jh];
#pragma unroll
        for (int mm = 0; mm < 16; ++mm) {
            int m = mg * 16 + mm;
            sC1o[m * 132 + jh] = fmaxf(a16[mm] + bc1, 0.0f);
        }
    }
    __syncthreads();

    // out = c1 @ W_c2^T + b_c2  (9 outputs/sample, 576 total)
    for (int idx = tid; idx < M_TILE * NACT; idx += NTHREADS) {
        int m = idx / NACT, o = idx - m * NACT;
        float a = b_c2[o];
#pragma unroll 1
        for (int k4 = 0; k4 < 32; ++k4) {
            float4 w = *(const float4*)(sWc2 + o * 132 + k4 * 4);
            float4 x = *(const float4*)(sC1o + m * 132 + k4 * 4);
            a = fmaf(w.x, x.x, a);
            a = fmaf(w.y, x.y, a);
            a = fmaf(w.z, x.z, a);
            a = fmaf(w.w, x.w, a);
        }
        out[sSamp[m] * NACT + o] = a;
    }
}

// ---------------- launch ----------------
extern "C" void kernel_launch(void* const* d_in, const int* in_sizes, int n_in,
                              void* d_out, int out_size) {
    const float* s    = (const float*)d_in[0];
    const float* W_os = (const float*)d_in[1];
    const float* b_os = (const float*)d_in[2];
    const float* W_ih = (const float*)d_in[3];
    const float* W_hh = (const float*)d_in[4];
    const float* b_ih = (const float*)d_in[5];
    const float* b_hh = (const float*)d_in[6];
    const float* W_ts = (const float*)d_in[7];
    const float* b_ts = (const float*)d_in[8];
    const float* W_c1 = (const float*)d_in[9];
    const float* b_c1 = (const float*)d_in[10];
    const float* W_c2 = (const float*)d_in[11];
    const float* b_c2 = (const float*)d_in[12];
    float* out = (float*)d_out;

    cudaFuncSetAttribute(k_main, cudaFuncAttributeMaxDynamicSharedMemorySize, SMEM_BYTES);

    k_count<<<B_TOT / 256, 256>>>(s);          // process launch idx 2 (harness has 2 before)
    k_prefix<<<1, 1>>>();                      // idx 3 (reads + re-zeroes hist)
    k_scatter<<<B_TOT / 256, 256>>>();         // idx 4
    k_main<<<NCTA, NTHREADS, SMEM_BYTES>>>(s, W_os, b_os, W_ih, W_hh, b_ih, b_hh,
                                           W_ts, b_ts, W_c1, b_c1, W_c2, b_c2, out);  // idx 5 -> ncu
}

// round 4
// speedup vs baseline: 2.0917x; 1.7046x over previous
#include <cuda_runtime.h>
#include <math.h>
#include <cstdint>

#define B_TOT   32768
#define T_STEPS 32
#define HID     128
#define GATES   512
#define OBS_OS  8
#define OBS_TS  6
#define SDIM    200     // 8 + 32*6
#define NACT    9
#define M_TILE  32
#define NTHREADS 512
#define NCTA    (B_TOT / M_TILE)

// ---------------- scratch (no allocations allowed) ----------------
__device__ int g_nobs[B_TOT];
__device__ int g_perm[B_TOT];
__device__ int g_hist[T_STEPS + 1];
__device__ int g_cursor[T_STEPS + 1];

// ---------------- shared-memory layout (float offsets) ----------------
#define O_BUFA  0                  // W chunk buf A [512][36]
#define O_BUFB  18432              // W chunk buf B [512][36]
#define O_EXCH  36864              // gate exchange [512][9]
#define O_SH    41472              // h [32][132]
#define O_SC    45696              // c [128][33]
#define O_SHOUT 49920              // h snapshot [32][128]
#define O_SX    54016              // x double buffer 2 x [32][8]
#define O_INT   54528              // nobs[32], samp[32]
#define O_X2    54592              // s_OS [32][8]
#define SMEM_FLOATS 54848
#define SMEM_BYTES  (SMEM_FLOATS * 4)
// head overlays
#define O_WTS   O_BUFA             // [128][132] (<= 18432)
#define O_WC2   O_BUFB             // [9][132]
#define O_XCAT  O_SH               // [32][256] = 8192 (ends before O_SHOUT)
#define O_C1    O_EXCH             // [32][132] = 4224 (<= 4608)

// ---------------- helpers ----------------
__device__ __forceinline__ unsigned smem_u32(const void* p) {
    unsigned r;
    asm("{ .reg .u64 t; cvta.to.shared.u64 t, %1; cvt.u32.u64 %0, t; }" : "=r"(r) : "l"(p));
    return r;
}
__device__ __forceinline__ void cpa16(unsigned dst, const void* src) {
    asm volatile("cp.async.cg.shared.global [%0], [%1], 16;" :: "r"(dst), "l"(src));
}
__device__ __forceinline__ void cpa4(unsigned dst, const void* src) {
    asm volatile("cp.async.ca.shared.global [%0], [%1], 4;" :: "r"(dst), "l"(src));
}
#define CP_COMMIT()  asm volatile("cp.async.commit_group;" ::: "memory")
#define CP_WAIT1()   asm volatile("cp.async.wait_group 1;" ::: "memory")
#define CP_WAIT0()   asm volatile("cp.async.wait_group 0;" ::: "memory")

__device__ __forceinline__ float tanhfast(float x) {
    float y; asm("tanh.approx.f32 %0, %1;" : "=f"(y) : "f"(x)); return y;
}
__device__ __forceinline__ float sigfast(float x) {
    return fmaf(tanhfast(0.5f * x), 0.5f, 0.5f);
}

// ---------------- pre-pass: length bucketing ----------------
__global__ void k_count(const float* __restrict__ s) {
    int m = blockIdx.x * blockDim.x + threadIdx.x;
    if (m >= B_TOT) return;
    const float* p = s + m * SDIM + OBS_OS;
    int cnt = 0;
#pragma unroll
    for (int t = 0; t < T_STEPS; ++t) {
        float v = p[t * OBS_TS];
        cnt += (v == v) ? 1 : 0;
    }
    g_nobs[m] = cnt;
    atomicAdd(&g_hist[cnt], 1);
}

__global__ void k_prefix() {
    int off = 0;
    for (int len = T_STEPS; len >= 0; --len) {
        g_cursor[len] = off;
        off += g_hist[len];
        g_hist[len] = 0;   // leave clean for next graph replay
    }
}

__global__ void k_scatter() {
    int m = blockIdx.x * blockDim.x + threadIdx.x;
    if (m >= B_TOT) return;
    int pos = atomicAdd(&g_cursor[g_nobs[m]], 1);
    g_perm[pos] = m;
}

// ---------------- fused main kernel ----------------
__global__ void __launch_bounds__(NTHREADS, 1)
k_main(const float* __restrict__ s,
       const float* __restrict__ W_os, const float* __restrict__ b_os,
       const float* __restrict__ W_ih, const float* __restrict__ W_hh,
       const float* __restrict__ b_ih, const float* __restrict__ b_hh,
       const float* __restrict__ W_ts, const float* __restrict__ b_ts,
       const float* __restrict__ W_c1, const float* __restrict__ b_c1,
       const float* __restrict__ W_c2, const float* __restrict__ b_c2,
       float* __restrict__ out)
{
    extern __shared__ float sm[];
    float* bufA  = sm + O_BUFA;
    float* bufB  = sm + O_BUFB;
    float* sE    = sm + O_EXCH;
    float* sH    = sm + O_SH;
    float* sC    = sm + O_SC;
    float* sHout = sm + O_SHOUT;
    float* sX    = sm + O_SX;
    float* sX2   = sm + O_X2;
    int*   sNobs = (int*)(sm + O_INT);
    int*   sSamp = sNobs + M_TILE;
    __shared__ int sTmaxS;

    const unsigned uBufA = smem_u32(bufA);
    const unsigned uBufB = smem_u32(bufB);
    const unsigned uSX   = smem_u32(sX);

    const int tid = threadIdx.x;
    const int j   = tid;          // gate row 0..511
    const int jh  = tid & 127;
    const int mg  = tid >> 7;     // 0..3
    const int base = blockIdx.x * M_TILE;

    if (tid < M_TILE) {
        int idx = g_perm[base + tid];
        sSamp[tid] = idx;
        sNobs[tid] = g_nobs[idx];
    }
    __syncthreads();

    // prologue prefetch: group0 = chunk0 + x(0), group1 = chunk1
    {
#pragma unroll
        for (int q = 0; q < 8; ++q) {
            int lin = q * NTHREADS + tid;
            int r = lin >> 3, cc = lin & 7;
            cpa16(uBufA + (unsigned)(r * 36 + cc * 4) * 4u,
                  W_hh + r * HID + 0 * 32 + cc * 4);
        }
        if (tid < M_TILE * OBS_TS) {
            int m = tid / OBS_TS, i = tid - m * OBS_TS;
            cpa4(uSX + (unsigned)(m * 8 + i) * 4u,
                 s + sSamp[m] * SDIM + OBS_OS + 0 * OBS_TS + i);
        }
        CP_COMMIT();
#pragma unroll
        for (int q = 0; q < 8; ++q) {
            int lin = q * NTHREADS + tid;
            int r = lin >> 3, cc = lin & 7;
            cpa16(uBufB + (unsigned)(r * 36 + cc * 4) * 4u,
                  W_hh + r * HID + 1 * 32 + cc * 4);
        }
        CP_COMMIT();
    }

    // zero state while prefetch flies
    for (int i = tid; i < 32 * 132; i += NTHREADS) sH[i] = 0.0f;
    for (int i = tid; i < 128 * 33; i += NTHREADS) sC[i] = 0.0f;
    for (int i = tid; i < 32 * 128; i += NTHREADS) sHout[i] = 0.0f;
    if (tid == 0) {
        int tm = 0;
        for (int m = 0; m < M_TILE; ++m) tm = max(tm, sNobs[m]);
        sTmaxS = tm;
    }

    float wih[OBS_TS];
#pragma unroll
    for (int i = 0; i < OBS_TS; ++i) wih[i] = W_ih[j * OBS_TS + i];
    const float bias = b_ih[j] + b_hh[j];
    __syncthreads();
    const int tmax = sTmaxS;

    // ================= LSTM recurrence =================
    for (int t = 0; t < tmax; ++t) {
        float* sXc = sX + (t & 1) * 256;

        float acc[M_TILE];
#pragma unroll
        for (int m = 0; m < M_TILE; ++m) acc[m] = bias;

#pragma unroll
        for (int c = 0; c < 4; ++c) {
            CP_WAIT1();
            __syncthreads();            // chunk c visible; prev buf readers done

            if (c == 0) {
                // sanitize x(t): NaN -> 0 (published by the next syncthreads)
                if (tid < M_TILE * OBS_TS) {
                    int m = tid / OBS_TS, i = tid - m * OBS_TS;
                    float v = sXc[m * 8 + i];
                    sXc[m * 8 + i] = (v == v) ? v : 0.0f;
                }
            }
            if (c == 1) {
                // x contribution (sXc sanitized + published at c==0 epilogue sync)
#pragma unroll
                for (int m = 0; m < M_TILE; ++m) {
                    float a = acc[m];
#pragma unroll
                    for (int i = 0; i < OBS_TS; ++i)
                        a = fmaf(wih[i], sXc[m * 8 + i], a);
                    acc[m] = a;
                }
            }

            const float* buf = (c & 1) ? bufB : bufA;
#pragma unroll 1
            for (int kk = 0; kk < 8; ++kk) {
                float4 w = *(const float4*)(buf + j * 36 + kk * 4);
                const float* hb = sH + c * 32 + kk * 4;
#pragma unroll
                for (int m = 0; m < M_TILE; ++m) {
                    float4 h = *(const float4*)(hb + m * 132);   // broadcast
                    float a = acc[m];
                    a = fmaf(w.x, h.x, a);
                    a = fmaf(w.y, h.y, a);
                    a = fmaf(w.z, h.z, a);
                    a = fmaf(w.w, h.w, a);
                    acc[m] = a;
                }
            }
            __syncthreads();            // all reads of this buf done

            // prefetch: c<2 -> chunks c+2 of this step; c>=2 -> chunks c-2 of step t+1
            int nc = (c + 2) & 3;
            unsigned ubuf = (c & 1) ? uBufB : uBufA;
#pragma unroll
            for (int q = 0; q < 8; ++q) {
                int lin = q * NTHREADS + tid;
                int r = lin >> 3, cc2 = lin & 7;
                cpa16(ubuf + (unsigned)(r * 36 + cc2 * 4) * 4u,
                      W_hh + r * HID + nc * 32 + cc2 * 4);
            }
            if (c == 2 && (t + 1) < tmax && tid < M_TILE * OBS_TS) {
                int m = tid / OBS_TS, i = tid - m * OBS_TS;
                cpa4(uSX + (unsigned)(((t + 1) & 1) * 256 + m * 8 + i) * 4u,
                     s + sSamp[m] * SDIM + OBS_OS + (t + 1) * OBS_TS + i);
            }
            CP_COMMIT();
        }

        // gate exchange + update: 4 passes of 8 samples (stride 9 -> conflict-free)
#pragma unroll
        for (int p = 0; p < 4; ++p) {
            if (p > 0) __syncthreads();      // prev pass readers done
#pragma unroll
            for (int q = 0; q < 8; ++q) sE[j * 9 + q] = acc[p * 8 + q];
            __syncthreads();
#pragma unroll
            for (int mm = 0; mm < 2; ++mm) {
                int mloc = mg * 2 + mm;
                int m = p * 8 + mloc;
                float gi = sE[(jh      ) * 9 + mloc];
                float gf = sE[(jh + 128) * 9 + mloc];
                float gg = sE[(jh + 256) * 9 + mloc];
                float go = sE[(jh + 384) * 9 + mloc];
                float iv = sigfast(gi), fv = sigfast(gf);
                float gv = tanhfast(gg), ov = sigfast(go);
                float cv = fmaf(fv, sC[jh * 33 + m], iv * gv);
                sC[jh * 33 + m] = cv;
                float hv = ov * tanhfast(cv);
                sH[m * 132 + jh] = hv;
                if (t == sNobs[m] - 1) sHout[m * 128 + jh] = hv;
            }
        }
        __syncthreads();   // sH updates visible before next step chunk0
    }

    CP_WAIT0();            // drain stray prefetches before overlaying buffers
    __syncthreads();

    // ================= head =================
    float* sWts  = sm + O_WTS;
    float* sWc2  = sm + O_WC2;
    float* sXcat = sm + O_XCAT;
    float* sC1o  = sm + O_C1;

    if (tid < M_TILE * OBS_OS) {
        int m = tid >> 3, i = tid & 7;
        sX2[tid] = s[sSamp[m] * SDIM + i];
    }
    // stage W_ts -> [r][132], coalesced
#pragma unroll
    for (int q = 0; q < 8; ++q) {
        int idx = q * NTHREADS + tid;       // 0..4095
        int r = idx >> 5, cc = idx & 31;
        *(float4*)(sWts + r * 132 + cc * 4) = *(const float4*)(W_ts + r * HID + cc * 4);
    }
    if (tid < NACT * 32) {
        int o = tid >> 5, kb = (tid & 31) * 4;
        *(float4*)(sWc2 + o * 132 + kb) = *(const float4*)(W_c2 + o * HID + kb);
    }
    __syncthreads();

    // x_OS = relu(s_OS @ W_os^T + b_os) -> xcat[:, :128]
    {
        float wos[8];
#pragma unroll
        for (int i = 0; i < 8; ++i) wos[i] = W_os[jh * 8 + i];
        float bos = b_os[jh];
#pragma unroll
        for (int mm = 0; mm < 8; ++mm) {
            int m = mg * 8 + mm;
            float a = bos;
#pragma unroll
            for (int i = 0; i < 8; ++i) a = fmaf(wos[i], sX2[m * 8 + i], a);
            sXcat[m * 256 + jh] = fmaxf(a, 0.0f);
        }
    }
    // x_TS = relu(hout @ W_ts^T + b_ts) -> xcat[:, 128:]
    {
        float a8[8] = {0,0,0,0,0,0,0,0};
#pragma unroll 1
        for (int k4 = 0; k4 < 32; ++k4) {
            float4 w = *(const float4*)(sWts + jh * 132 + k4 * 4);
#pragma unroll
            for (int mm = 0; mm < 8; ++mm) {
                int m = mg * 8 + mm;
                float4 h = *(const float4*)(sHout + m * 128 + k4 * 4);
                float a = a8[mm];
                a = fmaf(w.x, h.x, a);
                a = fmaf(w.y, h.y, a);
                a = fmaf(w.z, h.z, a);
                a = fmaf(w.w, h.w, a);
                a8[mm] = a;
            }
        }
        float bts = b_ts[jh];
#pragma unroll
        for (int mm = 0; mm < 8; ++mm) {
            int m = mg * 8 + mm;
            sXcat[m * 256 + HID + jh] = fmaxf(a8[mm] + bts, 0.0f);
        }
    }
    __syncthreads();

    // c1 = relu(xcat @ W_c1^T + b_c1), K=256 in two staged halves
    {
        float a8[8] = {0,0,0,0,0,0,0,0};
#pragma unroll 1
        for (int half = 0; half < 2; ++half) {
            __syncthreads();
#pragma unroll
            for (int q = 0; q < 8; ++q) {
                int idx = q * NTHREADS + tid;
                int r = idx >> 5, cc = idx & 31;
                *(float4*)(sWts + r * 132 + cc * 4) =
                    *(const float4*)(W_c1 + r * 256 + half * 128 + cc * 4);
            }
            __syncthreads();
#pragma unroll 1
            for (int k4 = 0; k4 < 32; ++k4) {
                float4 w = *(const float4*)(sWts + jh * 132 + k4 * 4);
#pragma unroll
                for (int mm = 0; mm < 8; ++mm) {
                    int m = mg * 8 + mm;
                    float4 x = *(const float4*)(sXcat + m * 256 + half * 128 + k4 * 4);
                    float a = a8[mm];
                    a = fmaf(w.x, x.x, a);
                    a = fmaf(w.y, x.y, a);
                    a = fmaf(w.z, x.z, a);
                    a = fmaf(w.w, x.w, a);
                    a8[mm] = a;
                }
            }
        }
        float bc1 = b_c1[jh];
#pragma unroll
        for (int mm = 0; mm < 8; ++mm) {
            int m = mg * 8 + mm;
            sC1o[m * 132 + jh] = fmaxf(a8[mm] + bc1, 0.0f);
        }
    }
    __syncthreads();

    // out = c1 @ W_c2^T + b_c2
    if (tid < M_TILE * NACT) {
        int m = tid / NACT, o = tid - m * NACT;
        float a = b_c2[o];
#pragma unroll 1
        for (int k4 = 0; k4 < 32; ++k4) {
            float4 w = *(const float4*)(sWc2 + o * 132 + k4 * 4);
            float4 x = *(const float4*)(sC1o + m * 132 + k4 * 4);
            a = fmaf(w.x, x.x, a);
            a = fmaf(w.y, x.y, a);
            a = fmaf(w.z, x.z, a);
            a = fmaf(w.w, x.w, a);
        }
        out[sSamp[m] * NACT + o] = a;
    }
}

// ---------------- launch ----------------
extern "C" void kernel_launch(void* const* d_in, const int* in_sizes, int n_in,
                              void* d_out, int out_size) {
    const float* s    = (const float*)d_in[0];
    const float* W_os = (const float*)d_in[1];
    const float* b_os = (const float*)d_in[2];
    const float* W_ih = (const float*)d_in[3];
    const float* W_hh = (const float*)d_in[4];
    const float* b_ih = (const float*)d_in[5];
    const float* b_hh = (const float*)d_in[6];
    const float* W_ts = (const float*)d_in[7];
    const float* b_ts = (const float*)d_in[8];
    const float* W_c1 = (const float*)d_in[9];
    const float* b_c1 = (const float*)d_in[10];
    const float* W_c2 = (const float*)d_in[11];
    const float* b_c2 = (const float*)d_in[12];
    float* out = (float*)d_out;

    cudaFuncSetAttribute(k_main, cudaFuncAttributeMaxDynamicSharedMemorySize, SMEM_BYTES);

    k_count<<<B_TOT / 256, 256>>>(s);
    k_prefix<<<1, 1>>>();
    k_scatter<<<B_TOT / 256, 256>>>();
    k_main<<<NCTA, NTHREADS, SMEM_BYTES>>>(s, W_os, b_os, W_ih, W_hh, b_ih, b_hh,
                                           W_ts, b_ts, W_c1, b_c1, W_c2, b_c2, out);
}

// round 5
// speedup vs baseline: 2.7909x; 1.3343x over previous
#include <cuda_runtime.h>
#include <math.h>
#include <cstdint>

#define B_TOT   32768
#define T_STEPS 32
#define HID     128
#define OBS_OS  8
#define OBS_TS  6
#define SDIM    200
#define NACT    9
#define M_TILE  32
#define NTHREADS 512
#define NCTA    (B_TOT / M_TILE)

typedef unsigned long long u64;

// ---------------- scratch ----------------
__device__ int g_nobs[B_TOT];
__device__ int g_perm[B_TOT];
__device__ int g_hist[T_STEPS + 1];
__device__ int g_cursor[T_STEPS + 1];

// ---------------- shared layout (float offsets) ----------------
#define O_BUFA  0                  // W chunk buf A [512][36]
#define O_BUFB  18432              // W chunk buf B [512][36]
#define O_EXCH  36864              // gate exchange [512][9]
#define O_HT    41472              // hT [k=128][36]  (m contiguous)
#define O_SC    46080              // c [128][33]
#define O_SHOUT 50304              // h snapshot [m=32][128]
#define O_SX    54400              // xT double buffer 2 x [6][36]
#define O_INT   54848              // nobs[32], samp[32]
#define O_X2    54912              // s_OS [32][8]
#define SMEM_FLOATS 55168
#define SMEM_BYTES  (SMEM_FLOATS * 4)
// head overlays
#define O_WTS   O_BUFA             // [128][132]
#define O_WC2   O_BUFB             // [9][132]
#define O_XCAT  O_HT               // [32][256] = 8192 (hT+sC region = 8832)
#define O_C1    O_EXCH             // [32][132] = 4224

// ---------------- helpers ----------------
__device__ __forceinline__ unsigned smem_u32(const void* p) {
    unsigned r;
    asm("{ .reg .u64 t; cvta.to.shared.u64 t, %1; cvt.u32.u64 %0, t; }" : "=r"(r) : "l"(p));
    return r;
}
__device__ __forceinline__ void cpa16(unsigned dst, const void* src) {
    asm volatile("cp.async.cg.shared.global [%0], [%1], 16;" :: "r"(dst), "l"(src));
}
__device__ __forceinline__ void cpa4(unsigned dst, const void* src) {
    asm volatile("cp.async.ca.shared.global [%0], [%1], 4;" :: "r"(dst), "l"(src));
}
#define CP_COMMIT()  asm volatile("cp.async.commit_group;" ::: "memory")
#define CP_WAIT1()   asm volatile("cp.async.wait_group 1;" ::: "memory")
#define CP_WAIT0()   asm volatile("cp.async.wait_group 0;" ::: "memory")

__device__ __forceinline__ void fma2(u64 &d, u64 a, u64 b) {
    asm("fma.rn.f32x2 %0, %1, %2, %0;" : "+l"(d) : "l"(a), "l"(b));
}
__device__ __forceinline__ u64 dup2(float a) {
    u64 r; asm("mov.b64 %0, {%1, %1};" : "=l"(r) : "f"(a)); return r;
}
__device__ __forceinline__ void unp2(u64 v, float &lo, float &hi) {
    asm("mov.b64 {%0, %1}, %2;" : "=f"(lo), "=f"(hi) : "l"(v));
}
__device__ __forceinline__ float tanhfast(float x) {
    float y; asm("tanh.approx.f32 %0, %1;" : "=f"(y) : "f"(x)); return y;
}
__device__ __forceinline__ float sigfast(float x) {
    return fmaf(tanhfast(0.5f * x), 0.5f, 0.5f);
}

// ---------------- pre-pass ----------------
__global__ void k_count(const float* __restrict__ s) {
    int m = blockIdx.x * blockDim.x + threadIdx.x;
    if (m >= B_TOT) return;
    const float* p = s + m * SDIM + OBS_OS;
    int cnt = 0;
#pragma unroll
    for (int t = 0; t < T_STEPS; ++t) {
        float v = p[t * OBS_TS];
        cnt += (v == v) ? 1 : 0;
    }
    g_nobs[m] = cnt;
    atomicAdd(&g_hist[cnt], 1);
}

__global__ void k_prefix() {
    int off = 0;
    for (int len = T_STEPS; len >= 0; --len) {
        g_cursor[len] = off;
        off += g_hist[len];
        g_hist[len] = 0;
    }
}

__global__ void k_scatter() {
    int m = blockIdx.x * blockDim.x + threadIdx.x;
    if (m >= B_TOT) return;
    int pos = atomicAdd(&g_cursor[g_nobs[m]], 1);
    g_perm[pos] = m;
}

// ---------------- fused main kernel ----------------
__global__ void __launch_bounds__(NTHREADS, 1)
k_main(const float* __restrict__ s,
       const float* __restrict__ W_os, const float* __restrict__ b_os,
       const float* __restrict__ W_ih, const float* __restrict__ W_hh,
       const float* __restrict__ b_ih, const float* __restrict__ b_hh,
       const float* __restrict__ W_ts, const float* __restrict__ b_ts,
       const float* __restrict__ W_c1, const float* __restrict__ b_c1,
       const float* __restrict__ W_c2, const float* __restrict__ b_c2,
       float* __restrict__ out)
{
    extern __shared__ float sm[];
    float* bufA  = sm + O_BUFA;
    float* bufB  = sm + O_BUFB;
    float* sE    = sm + O_EXCH;
    float* hT    = sm + O_HT;
    float* sC    = sm + O_SC;
    float* sHout = sm + O_SHOUT;
    float* sX    = sm + O_SX;     // xT double buffer, stride 216 per buffer
    float* sX2   = sm + O_X2;
    int*   sNobs = (int*)(sm + O_INT);
    int*   sSamp = sNobs + M_TILE;
    __shared__ int sTmaxS;

    const unsigned uBufA = smem_u32(bufA);
    const unsigned uBufB = smem_u32(bufB);
    const unsigned uSX   = smem_u32(sX);

    const int tid = threadIdx.x;
    const int jr  = tid & 255;    // base gate row; thread owns jr and jr+256
    const int sg  = tid >> 8;     // sample half: 0 -> m 0..15, 1 -> m 16..31
    const int jh  = tid & 127;    // for update/head phases
    const int mg  = tid >> 7;     // 0..3
    const int base = blockIdx.x * M_TILE;

    if (tid < M_TILE) {
        int idx = g_perm[base + tid];
        sSamp[tid] = idx;
        sNobs[tid] = g_nobs[idx];
    }
    __syncthreads();

    // prologue prefetch: group0 = chunk0 + xT(0); group1 = chunk1
    {
#pragma unroll
        for (int q = 0; q < 8; ++q) {
            int lin = q * NTHREADS + tid;
            int r = lin >> 3, cc = lin & 7;
            cpa16(uBufA + (unsigned)(r * 36 + cc * 4) * 4u,
                  W_hh + r * HID + 0 * 32 + cc * 4);
        }
        if (tid < M_TILE * OBS_TS) {
            int m = tid / OBS_TS, i = tid - m * OBS_TS;
            cpa4(uSX + (unsigned)(i * 36 + m) * 4u,
                 s + sSamp[m] * SDIM + OBS_OS + 0 * OBS_TS + i);
        }
        CP_COMMIT();
#pragma unroll
        for (int q = 0; q < 8; ++q) {
            int lin = q * NTHREADS + tid;
            int r = lin >> 3, cc = lin & 7;
            cpa16(uBufB + (unsigned)(r * 36 + cc * 4) * 4u,
                  W_hh + r * HID + 1 * 32 + cc * 4);
        }
        CP_COMMIT();
    }

    // zero state while prefetch flies
    for (int i = tid; i < 128 * 36; i += NTHREADS) hT[i] = 0.0f;
    for (int i = tid; i < 128 * 33; i += NTHREADS) sC[i] = 0.0f;
    for (int i = tid; i < 32 * 128; i += NTHREADS) sHout[i] = 0.0f;
    if (tid == 0) {
        int tm = 0;
        for (int m = 0; m < M_TILE; ++m) tm = max(tm, sNobs[m]);
        sTmaxS = tm;
    }

    float wihA[OBS_TS], wihB[OBS_TS];
#pragma unroll
    for (int i = 0; i < OBS_TS; ++i) {
        wihA[i] = W_ih[jr * OBS_TS + i];
        wihB[i] = W_ih[(jr + 256) * OBS_TS + i];
    }
    const float biasA = b_ih[jr] + b_hh[jr];
    const float biasB = b_ih[jr + 256] + b_hh[jr + 256];
    __syncthreads();
    const int tmax = sTmaxS;

    // ================= LSTM recurrence =================
    for (int t = 0; t < tmax; ++t) {
        float* xTc = sX + (t & 1) * 216;

        u64 acc0[8], acc1[8];   // (row jr | row jr+256) x 16 samples as m-pairs
        {
            u64 bA = dup2(biasA), bB = dup2(biasB);
#pragma unroll
            for (int q = 0; q < 8; ++q) { acc0[q] = bA; acc1[q] = bB; }
        }

#pragma unroll
        for (int c = 0; c < 4; ++c) {
            CP_WAIT1();
            __syncthreads();            // chunk c visible; prev buf readers done

            if (c == 0) {
                // sanitize xT(t): NaN -> 0 (published by c==1's barrier)
                if (tid < M_TILE * OBS_TS) {
                    int m = tid / OBS_TS, i = tid - m * OBS_TS;
                    float v = xTc[i * 36 + m];
                    xTc[i * 36 + m] = (v == v) ? v : 0.0f;
                }
            }
            if (c == 1) {
                // x contribution (packed over m-pairs)
#pragma unroll
                for (int i = 0; i < OBS_TS; ++i) {
                    u64 wA = dup2(wihA[i]), wB = dup2(wihB[i]);
                    const ulonglong2* xp = (const ulonglong2*)(xTc + i * 36 + sg * 16);
#pragma unroll
                    for (int m4 = 0; m4 < 4; ++m4) {
                        ulonglong2 xx = xp[m4];
                        fma2(acc0[m4 * 2],     wA, xx.x);
                        fma2(acc0[m4 * 2 + 1], wA, xx.y);
                        fma2(acc1[m4 * 2],     wB, xx.x);
                        fma2(acc1[m4 * 2 + 1], wB, xx.y);
                    }
                }
            }

            const float* buf = (c & 1) ? bufB : bufA;
#pragma unroll 1
            for (int kk = 0; kk < 8; ++kk) {
                float4 w0 = *(const float4*)(buf + jr * 36 + kk * 4);
                float4 w1 = *(const float4*)(buf + (jr + 256) * 36 + kk * 4);
                const float* hb = hT + (c * 32 + kk * 4) * 36 + sg * 16;
#pragma unroll
                for (int q = 0; q < 4; ++q) {
                    float w0q = (q == 0) ? w0.x : (q == 1) ? w0.y : (q == 2) ? w0.z : w0.w;
                    float w1q = (q == 0) ? w1.x : (q == 1) ? w1.y : (q == 2) ? w1.z : w1.w;
                    u64 wA = dup2(w0q), wB = dup2(w1q);
                    const ulonglong2* hp = (const ulonglong2*)(hb + q * 36);
#pragma unroll
                    for (int m4 = 0; m4 < 4; ++m4) {
                        ulonglong2 hh = hp[m4];
                        fma2(acc0[m4 * 2],     wA, hh.x);
                        fma2(acc0[m4 * 2 + 1], wA, hh.y);
                        fma2(acc1[m4 * 2],     wB, hh.x);
                        fma2(acc1[m4 * 2 + 1], wB, hh.y);
                    }
                }
            }
            __syncthreads();            // all reads of this buf done

            // prefetch next chunk (c+2 of this step / c-2 of step t+1)
            int nc = (c + 2) & 3;
            unsigned ubuf = (c & 1) ? uBufB : uBufA;
#pragma unroll
            for (int q = 0; q < 8; ++q) {
                int lin = q * NTHREADS + tid;
                int r = lin >> 3, cc2 = lin & 7;
                cpa16(ubuf + (unsigned)(r * 36 + cc2 * 4) * 4u,
                      W_hh + r * HID + nc * 32 + cc2 * 4);
            }
            if (c == 2 && (t + 1) < tmax && tid < M_TILE * OBS_TS) {
                int m = tid / OBS_TS, i = tid - m * OBS_TS;
                cpa4(uSX + (unsigned)(((t + 1) & 1) * 216 + i * 36 + m) * 4u,
                     s + sSamp[m] * SDIM + OBS_OS + (t + 1) * OBS_TS + i);
            }
            CP_COMMIT();
        }

        // gate exchange + update: 4 passes of 8 samples (stride 9, conflict-free)
#pragma unroll
        for (int p = 0; p < 4; ++p) {
            if (p > 0) __syncthreads();
            if ((tid >> 8) == (p >> 1)) {       // this thread holds pass-p samples
#pragma unroll
                for (int q4 = 0; q4 < 4; ++q4) {
                    float lo, hi;
                    unp2(acc0[(p & 1) * 4 + q4], lo, hi);
                    sE[jr * 9 + q4 * 2] = lo;
                    sE[jr * 9 + q4 * 2 + 1] = hi;
                    unp2(acc1[(p & 1) * 4 + q4], lo, hi);
                    sE[(jr + 256) * 9 + q4 * 2] = lo;
                    sE[(jr + 256) * 9 + q4 * 2 + 1] = hi;
                }
            }
            __syncthreads();
#pragma unroll
            for (int mm = 0; mm < 2; ++mm) {
                int mloc = mg * 2 + mm;
                int m = p * 8 + mloc;
                float gi = sE[(jh      ) * 9 + mloc];
                float gf = sE[(jh + 128) * 9 + mloc];
                float gg = sE[(jh + 256) * 9 + mloc];
                float go = sE[(jh + 384) * 9 + mloc];
                float iv = sigfast(gi), fv = sigfast(gf);
                float gv = tanhfast(gg), ov = sigfast(go);
                float cv = fmaf(fv, sC[jh * 33 + m], iv * gv);
                sC[jh * 33 + m] = cv;
                float hv = ov * tanhfast(cv);
                hT[jh * 36 + m] = hv;           // transposed h
                if (t == sNobs[m] - 1) sHout[m * 128 + jh] = hv;
            }
        }
        __syncthreads();
    }

    CP_WAIT0();
    __syncthreads();

    // ================= head =================
    float* sWts  = sm + O_WTS;
    float* sWc2  = sm + O_WC2;
    float* sXcat = sm + O_XCAT;
    float* sC1o  = sm + O_C1;

    if (tid < M_TILE * OBS_OS) {
        int m = tid >> 3, i = tid & 7;
        sX2[tid] = s[sSamp[m] * SDIM + i];
    }
#pragma unroll
    for (int q = 0; q < 8; ++q) {
        int idx = q * NTHREADS + tid;
        int r = idx >> 5, cc = idx & 31;
        *(float4*)(sWts + r * 132 + cc * 4) = *(const float4*)(W_ts + r * HID + cc * 4);
    }
    if (tid < NACT * 32) {
        int o = tid >> 5, kb = (tid & 31) * 4;
        *(float4*)(sWc2 + o * 132 + kb) = *(const float4*)(W_c2 + o * HID + kb);
    }
    __syncthreads();

    // x_OS = relu(s_OS @ W_os^T + b_os)
    {
        float wos[8];
#pragma unroll
        for (int i = 0; i < 8; ++i) wos[i] = W_os[jh * 8 + i];
        float bos = b_os[jh];
#pragma unroll
        for (int mm = 0; mm < 8; ++mm) {
            int m = mg * 8 + mm;
            float a = bos;
#pragma unroll
            for (int i = 0; i < 8; ++i) a = fmaf(wos[i], sX2[m * 8 + i], a);
            sXcat[m * 256 + jh] = fmaxf(a, 0.0f);
        }
    }
    // x_TS = relu(hout @ W_ts^T + b_ts)
    {
        float a8[8] = {0,0,0,0,0,0,0,0};
#pragma unroll 1
        for (int k4 = 0; k4 < 32; ++k4) {
            float4 w = *(const float4*)(sWts + jh * 132 + k4 * 4);
#pragma unroll
            for (int mm = 0; mm < 8; ++mm) {
                int m = mg * 8 + mm;
                float4 h = *(const float4*)(sHout + m * 128 + k4 * 4);
                float a = a8[mm];
                a = fmaf(w.x, h.x, a);
                a = fmaf(w.y, h.y, a);
                a = fmaf(w.z, h.z, a);
                a = fmaf(w.w, h.w, a);
                a8[mm] = a;
            }
        }
        float bts = b_ts[jh];
#pragma unroll
        for (int mm = 0; mm < 8; ++mm) {
            int m = mg * 8 + mm;
            sXcat[m * 256 + HID + jh] = fmaxf(a8[mm] + bts, 0.0f);
        }
    }
    __syncthreads();

    // c1 = relu(xcat @ W_c1^T + b_c1)
    {
        float a8[8] = {0,0,0,0,0,0,0,0};
#pragma unroll 1
        for (int half = 0; half < 2; ++half) {
            __syncthreads();
#pragma unroll
            for (int q = 0; q < 8; ++q) {
                int idx = q * NTHREADS + tid;
                int r = idx >> 5, cc = idx & 31;
                *(float4*)(sWts + r * 132 + cc * 4) =
                    *(const float4*)(W_c1 + r * 256 + half * 128 + cc * 4);
            }
            __syncthreads();
#pragma unroll 1
            for (int k4 = 0; k4 < 32; ++k4) {
                float4 w = *(const float4*)(sWts + jh * 132 + k4 * 4);
#pragma unroll
                for (int mm = 0; mm < 8; ++mm) {
                    int m = mg * 8 + mm;
                    float4 x = *(const float4*)(sXcat + m * 256 + half * 128 + k4 * 4);
                    float a = a8[mm];
                    a = fmaf(w.x, x.x, a);
                    a = fmaf(w.y, x.y, a);
                    a = fmaf(w.z, x.z, a);
                    a = fmaf(w.w, x.w, a);
                    a8[mm] = a;
                }
            }
        }
        float bc1 = b_c1[jh];
#pragma unroll
        for (int mm = 0; mm < 8; ++mm) {
            int m = mg * 8 + mm;
            sC1o[m * 132 + jh] = fmaxf(a8[mm] + bc1, 0.0f);
        }
    }
    __syncthreads();

    if (tid < M_TILE * NACT) {
        int m = tid / NACT, o = tid - m * NACT;
        float a = b_c2[o];
#pragma unroll 1
        for (int k4 = 0; k4 < 32; ++k4) {
            float4 w = *(const float4*)(sWc2 + o * 132 + k4 * 4);
            float4 x = *(const float4*)(sC1o + m * 132 + k4 * 4);
            a = fmaf(w.x, x.x, a);
            a = fmaf(w.y, x.y, a);
            a = fmaf(w.z, x.z, a);
            a = fmaf(w.w, x.w, a);
        }
        out[sSamp[m] * NACT + o] = a;
    }
}

// ---------------- launch ----------------
extern "C" void kernel_launch(void* const* d_in, const int* in_sizes, int n_in,
                              void* d_out, int out_size) {
    const float* s    = (const float*)d_in[0];
    const float* W_os = (const float*)d_in[1];
    const float* b_os = (const float*)d_in[2];
    const float* W_ih = (const float*)d_in[3];
    const float* W_hh = (const float*)d_in[4];
    const float* b_ih = (const float*)d_in[5];
    const float* b_hh = (const float*)d_in[6];
    const float* W_ts = (const float*)d_in[7];
    const float* b_ts = (const float*)d_in[8];
    const float* W_c1 = (const float*)d_in[9];
    const float* b_c1 = (const float*)d_in[10];
    const float* W_c2 = (const float*)d_in[11];
    const float* b_c2 = (const float*)d_in[12];
    float* out = (float*)d_out;

    cudaFuncSetAttribute(k_main, cudaFuncAttributeMaxDynamicSharedMemorySize, SMEM_BYTES);

    k_count<<<B_TOT / 256, 256>>>(s);
    k_prefix<<<1, 1>>>();
    k_scatter<<<B_TOT / 256, 256>>>();
    k_main<<<NCTA, NTHREADS, SMEM_BYTES>>>(s, W_os, b_os, W_ih, W_hh, b_ih, b_hh,
                                           W_ts, b_ts, W_c1, b_c1, W_c2, b_c2, out);
}

// round 6
// speedup vs baseline: 2.9677x; 1.0634x over previous
#include <cuda_runtime.h>
#include <math.h>
#include <cstdint>

#define B_TOT   32768
#define T_STEPS 32
#define HID     128
#define OBS_OS  8
#define OBS_TS  6
#define SDIM    200
#define NACT    9
#define M_TILE  32
#define NTHREADS 512
#define NCTA    (B_TOT / M_TILE)

typedef unsigned long long u64;

// ---------------- scratch ----------------
__device__ int g_nobs[B_TOT];
__device__ int g_perm[B_TOT];
__device__ int g_hist[T_STEPS + 1];
__device__ int g_cursor[T_STEPS + 1];

// ---------------- shared layout (float offsets) ----------------
#define O_BUFA  0                  // W chunk buf A [512][36]
#define O_BUFB  18432              // W chunk buf B [512][36]
#define O_WIH   36864              // W_ih staged [512][8] (cols 0..5 used)
#define O_HT    40960              // hT [k=128][36] (m contiguous)
#define O_SHOUT 45568              // h snapshot [m=32][128]
#define O_SX    49664              // xT double buffer 2 x [6][36]
#define O_INT   50096              // nobs[32], samp[32]
#define O_X2    50160              // s_OS [32][8]
#define SMEM_FLOATS 50416
#define SMEM_BYTES  (SMEM_FLOATS * 4)
// head overlays
#define O_WTS   O_BUFA             // [128][132] = 16896
#define O_XCAT  O_BUFB             // [32][256] = 8192
#define O_WC2   (O_BUFB + 8192)    // [9][132] = 1188
#define O_C1    (O_BUFB + 9408)    // [32][132] = 4224 (ends 13632 < 18432)

// ---------------- helpers ----------------
__device__ __forceinline__ unsigned smem_u32(const void* p) {
    unsigned r;
    asm("{ .reg .u64 t; cvta.to.shared.u64 t, %1; cvt.u32.u64 %0, t; }" : "=r"(r) : "l"(p));
    return r;
}
__device__ __forceinline__ void cpa16(unsigned dst, const void* src) {
    asm volatile("cp.async.cg.shared.global [%0], [%1], 16;" :: "r"(dst), "l"(src));
}
__device__ __forceinline__ void cpa4(unsigned dst, const void* src) {
    asm volatile("cp.async.ca.shared.global [%0], [%1], 4;" :: "r"(dst), "l"(src));
}
#define CP_COMMIT()  asm volatile("cp.async.commit_group;" ::: "memory")
#define CP_WAIT1()   asm volatile("cp.async.wait_group 1;" ::: "memory")
#define CP_WAIT0()   asm volatile("cp.async.wait_group 0;" ::: "memory")

__device__ __forceinline__ void fma2(u64 &d, u64 a, u64 b) {
    asm("fma.rn.f32x2 %0, %1, %2, %0;" : "+l"(d) : "l"(a), "l"(b));
}
__device__ __forceinline__ u64 dup2(float a) {
    u64 r; asm("mov.b64 %0, {%1, %1};" : "=l"(r) : "f"(a)); return r;
}
__device__ __forceinline__ void unp2(u64 v, float &lo, float &hi) {
    asm("mov.b64 {%0, %1}, %2;" : "=f"(lo), "=f"(hi) : "l"(v));
}
__device__ __forceinline__ float tanhfast(float x) {
    float y; asm("tanh.approx.f32 %0, %1;" : "=f"(y) : "f"(x)); return y;
}
__device__ __forceinline__ float sigfast(float x) {
    return fmaf(tanhfast(0.5f * x), 0.5f, 0.5f);
}

// ---------------- pre-pass ----------------
__global__ void k_count(const float* __restrict__ s) {
    int m = blockIdx.x * blockDim.x + threadIdx.x;
    if (m >= B_TOT) return;
    const float* p = s + m * SDIM + OBS_OS;
    int cnt = 0;
#pragma unroll
    for (int t = 0; t < T_STEPS; ++t) {
        float v = p[t * OBS_TS];
        cnt += (v == v) ? 1 : 0;
    }
    g_nobs[m] = cnt;
    atomicAdd(&g_hist[cnt], 1);
}

__global__ void k_prefix() {
    int off = 0;
    for (int len = T_STEPS; len >= 0; --len) {
        g_cursor[len] = off;
        off += g_hist[len];
        g_hist[len] = 0;
    }
}

__global__ void k_scatter() {
    int m = blockIdx.x * blockDim.x + threadIdx.x;
    if (m >= B_TOT) return;
    int pos = atomicAdd(&g_cursor[g_nobs[m]], 1);
    g_perm[pos] = m;
}

// ---------------- fused main kernel ----------------
__global__ void __launch_bounds__(NTHREADS, 1)
k_main(const float* __restrict__ s,
       const float* __restrict__ W_os, const float* __restrict__ b_os,
       const float* __restrict__ W_ih, const float* __restrict__ W_hh,
       const float* __restrict__ b_ih, const float* __restrict__ b_hh,
       const float* __restrict__ W_ts, const float* __restrict__ b_ts,
       const float* __restrict__ W_c1, const float* __restrict__ b_c1,
       const float* __restrict__ W_c2, const float* __restrict__ b_c2,
       float* __restrict__ out)
{
    extern __shared__ float sm[];
    float* bufA  = sm + O_BUFA;
    float* bufB  = sm + O_BUFB;
    float* sWih  = sm + O_WIH;
    float* hT    = sm + O_HT;
    float* sHout = sm + O_SHOUT;
    float* sX    = sm + O_SX;
    float* sX2   = sm + O_X2;
    int*   sNobs = (int*)(sm + O_INT);
    int*   sSamp = sNobs + M_TILE;
    __shared__ int sTmaxS;

    const unsigned uBufA = smem_u32(bufA);
    const unsigned uBufB = smem_u32(bufB);
    const unsigned uSX   = smem_u32(sX);

    const int tid = threadIdx.x;
    const int jh  = tid & 127;    // hidden unit (thread owns gate rows jh+128g, g=0..3)
    const int mg  = tid >> 7;     // sample group: samples mg*8 .. mg*8+7
    const int base = blockIdx.x * M_TILE;

    if (tid < M_TILE) {
        int idx = g_perm[base + tid];
        sSamp[tid] = idx;
        sNobs[tid] = g_nobs[idx];
    }
    __syncthreads();

    // prologue prefetch: group0 = chunk0 + xT(0); group1 = chunk1
#pragma unroll
    for (int q = 0; q < 8; ++q) {
        int lin = q * NTHREADS + tid;
        int r = lin >> 3, cc = lin & 7;
        cpa16(uBufA + (unsigned)(r * 36 + cc * 4) * 4u,
              W_hh + r * HID + 0 * 32 + cc * 4);
    }
    if (tid < M_TILE * OBS_TS) {
        int m = tid / OBS_TS, i = tid - m * OBS_TS;
        cpa4(uSX + (unsigned)(i * 36 + m) * 4u,
             s + sSamp[m] * SDIM + OBS_OS + 0 * OBS_TS + i);
    }
    CP_COMMIT();
#pragma unroll
    for (int q = 0; q < 8; ++q) {
        int lin = q * NTHREADS + tid;
        int r = lin >> 3, cc = lin & 7;
        cpa16(uBufB + (unsigned)(r * 36 + cc * 4) * 4u,
              W_hh + r * HID + 1 * 32 + cc * 4);
    }
    CP_COMMIT();

    // stage W_ih [512][8] (cols 6,7 zero) + zero state while prefetch flies
#pragma unroll
    for (int q = 0; q < 8; ++q) {
        int idx = q * NTHREADS + tid;     // 0..4095
        int r = idx >> 3, col = idx & 7;
        sWih[idx] = (col < OBS_TS) ? W_ih[r * OBS_TS + col] : 0.0f;
    }
    for (int i = tid; i < 128 * 36; i += NTHREADS) hT[i] = 0.0f;
    for (int i = tid; i < 32 * 128; i += NTHREADS) sHout[i] = 0.0f;
    if (tid == 0) {
        int tm = 0;
        for (int m = 0; m < M_TILE; ++m) tm = max(tm, sNobs[m]);
        sTmaxS = tm;
    }

    float biasv[4];
#pragma unroll
    for (int g = 0; g < 4; ++g)
        biasv[g] = b_ih[jh + 128 * g] + b_hh[jh + 128 * g];
    float creg[8];
#pragma unroll
    for (int e = 0; e < 8; ++e) creg[e] = 0.0f;

    __syncthreads();
    const int tmax = sTmaxS;

    // ================= LSTM recurrence =================
    for (int t = 0; t < tmax; ++t) {
        float* xTc = sX + (t & 1) * 216;

        u64 aI[4], aF[4], aG[4], aO[4];   // 4 m-pairs each (8 samples)
        {
            u64 bi = dup2(biasv[0]), bf = dup2(biasv[1]);
            u64 bg = dup2(biasv[2]), bo = dup2(biasv[3]);
#pragma unroll
            for (int p = 0; p < 4; ++p) { aI[p] = bi; aF[p] = bf; aG[p] = bg; aO[p] = bo; }
        }

#pragma unroll
        for (int c = 0; c < 4; ++c) {
            CP_WAIT1();
            __syncthreads();            // chunk c visible; prev buf readers done; hT(t) published

            if (c == 0) {
                // sanitize xT(t): NaN -> 0 (consumed at c==1 after its barrier)
                if (tid < M_TILE * OBS_TS) {
                    int m = tid / OBS_TS, i = tid - m * OBS_TS;
                    float v = xTc[i * 36 + m];
                    xTc[i * 36 + m] = (v == v) ? v : 0.0f;
                }
            }
            if (c == 1) {
                // x contribution
#pragma unroll
                for (int i = 0; i < OBS_TS; ++i) {
                    u64 wi = dup2(sWih[(jh      ) * 8 + i]);
                    u64 wf = dup2(sWih[(jh + 128) * 8 + i]);
                    u64 wg = dup2(sWih[(jh + 256) * 8 + i]);
                    u64 wo = dup2(sWih[(jh + 384) * 8 + i]);
                    const ulonglong2* xp = (const ulonglong2*)(xTc + i * 36 + mg * 8);
                    ulonglong2 x01 = xp[0], x23 = xp[1];
                    fma2(aI[0], wi, x01.x); fma2(aI[1], wi, x01.y);
                    fma2(aI[2], wi, x23.x); fma2(aI[3], wi, x23.y);
                    fma2(aF[0], wf, x01.x); fma2(aF[1], wf, x01.y);
                    fma2(aF[2], wf, x23.x); fma2(aF[3], wf, x23.y);
                    fma2(aG[0], wg, x01.x); fma2(aG[1], wg, x01.y);
                    fma2(aG[2], wg, x23.x); fma2(aG[3], wg, x23.y);
                    fma2(aO[0], wo, x01.x); fma2(aO[1], wo, x01.y);
                    fma2(aO[2], wo, x23.x); fma2(aO[3], wo, x23.y);
                }
            }

            const float* buf = (c & 1) ? bufB : bufA;
#pragma unroll 1
            for (int kk = 0; kk < 8; ++kk) {
                float4 wI = *(const float4*)(buf + (jh      ) * 36 + kk * 4);
                float4 wF = *(const float4*)(buf + (jh + 128) * 36 + kk * 4);
                float4 wG = *(const float4*)(buf + (jh + 256) * 36 + kk * 4);
                float4 wO = *(const float4*)(buf + (jh + 384) * 36 + kk * 4);
                const float* hb = hT + (c * 32 + kk * 4) * 36 + mg * 8;
#pragma unroll
                for (int q = 0; q < 4; ++q) {
                    const ulonglong2* hp = (const ulonglong2*)(hb + q * 36);
                    ulonglong2 h01 = hp[0], h23 = hp[1];
                    float wIq = (q == 0) ? wI.x : (q == 1) ? wI.y : (q == 2) ? wI.z : wI.w;
                    float wFq = (q == 0) ? wF.x : (q == 1) ? wF.y : (q == 2) ? wF.z : wF.w;
                    float wGq = (q == 0) ? wG.x : (q == 1) ? wG.y : (q == 2) ? wG.z : wG.w;
                    float wOq = (q == 0) ? wO.x : (q == 1) ? wO.y : (q == 2) ? wO.z : wO.w;
                    u64 wi = dup2(wIq), wf = dup2(wFq), wg = dup2(wGq), wo = dup2(wOq);
                    fma2(aI[0], wi, h01.x); fma2(aI[1], wi, h01.y);
                    fma2(aI[2], wi, h23.x); fma2(aI[3], wi, h23.y);
                    fma2(aF[0], wf, h01.x); fma2(aF[1], wf, h01.y);
                    fma2(aF[2], wf, h23.x); fma2(aF[3], wf, h23.y);
                    fma2(aG[0], wg, h01.x); fma2(aG[1], wg, h01.y);
                    fma2(aG[2], wg, h23.x); fma2(aG[3], wg, h23.y);
                    fma2(aO[0], wo, h01.x); fma2(aO[1], wo, h01.y);
                    fma2(aO[2], wo, h23.x); fma2(aO[3], wo, h23.y);
                }
            }
            __syncthreads();            // all reads of this buf + hT chunk done

            // prefetch next chunk (c+2 of this step / c-2 of step t+1)
            int nc = (c + 2) & 3;
            unsigned ubuf = (c & 1) ? uBufB : uBufA;
#pragma unroll
            for (int q = 0; q < 8; ++q) {
                int lin = q * NTHREADS + tid;
                int r = lin >> 3, cc2 = lin & 7;
                cpa16(ubuf + (unsigned)(r * 36 + cc2 * 4) * 4u,
                      W_hh + r * HID + nc * 32 + cc2 * 4);
            }
            if (c == 2 && (t + 1) < tmax && tid < M_TILE * OBS_TS) {
                int m = tid / OBS_TS, i = tid - m * OBS_TS;
                cpa4(uSX + (unsigned)(((t + 1) & 1) * 216 + i * 36 + m) * 4u,
                     s + sSamp[m] * SDIM + OBS_OS + (t + 1) * OBS_TS + i);
            }
            CP_COMMIT();
        }

        // update: all 4 gates for (jh, 8 samples) are in registers — no exchange
#pragma unroll
        for (int p = 0; p < 4; ++p) {
            float i0, i1, f0, f1, g0, g1, o0, o1;
            unp2(aI[p], i0, i1);
            unp2(aF[p], f0, f1);
            unp2(aG[p], g0, g1);
            unp2(aO[p], o0, o1);
#pragma unroll
            for (int e = 0; e < 2; ++e) {
                int sloc = p * 2 + e;
                int m = mg * 8 + sloc;
                float gi = e ? i1 : i0, gf = e ? f1 : f0;
                float gg = e ? g1 : g0, go = e ? o1 : o0;
                float iv = sigfast(gi), fv = sigfast(gf);
                float gv = tanhfast(gg), ov = sigfast(go);
                float cv = fmaf(fv, creg[sloc], iv * gv);
                creg[sloc] = cv;
                float hv = ov * tanhfast(cv);
                hT[jh * 36 + m] = hv;
                if (t == sNobs[m] - 1) sHout[m * 128 + jh] = hv;
            }
        }
        // no barrier: next step's chunk-0 top barrier publishes hT
    }

    CP_WAIT0();
    __syncthreads();

    // ================= head =================
    float* sWts  = sm + O_WTS;
    float* sWc2  = sm + O_WC2;
    float* sXcat = sm + O_XCAT;
    float* sC1o  = sm + O_C1;

    if (tid < M_TILE * OBS_OS) {
        int m = tid >> 3, i = tid & 7;
        sX2[tid] = s[sSamp[m] * SDIM + i];
    }
#pragma unroll
    for (int q = 0; q < 8; ++q) {
        int idx = q * NTHREADS + tid;
        int r = idx >> 5, cc = idx & 31;
        *(float4*)(sWts + r * 132 + cc * 4) = *(const float4*)(W_ts + r * HID + cc * 4);
    }
    if (tid < NACT * 32) {
        int o = tid >> 5, kb = (tid & 31) * 4;
        *(float4*)(sWc2 + o * 132 + kb) = *(const float4*)(W_c2 + o * HID + kb);
    }
    __syncthreads();

    // x_OS = relu(s_OS @ W_os^T + b_os)
    {
        float wos[8];
#pragma unroll
        for (int i = 0; i < 8; ++i) wos[i] = W_os[jh * 8 + i];
        float bos = b_os[jh];
#pragma unroll
        for (int mm = 0; mm < 8; ++mm) {
            int m = mg * 8 + mm;
            float a = bos;
#pragma unroll
            for (int i = 0; i < 8; ++i) a = fmaf(wos[i], sX2[m * 8 + i], a);
            sXcat[m * 256 + jh] = fmaxf(a, 0.0f);
        }
    }
    // x_TS = relu(hout @ W_ts^T + b_ts)
    {
        float a8[8] = {0,0,0,0,0,0,0,0};
#pragma unroll 1
        for (int k4 = 0; k4 < 32; ++k4) {
            float4 w = *(const float4*)(sWts + jh * 132 + k4 * 4);
#pragma unroll
            for (int mm = 0; mm < 8; ++mm) {
                int m = mg * 8 + mm;
                float4 h = *(const float4*)(sHout + m * 128 + k4 * 4);
                float a = a8[mm];
                a = fmaf(w.x, h.x, a);
                a = fmaf(w.y, h.y, a);
                a = fmaf(w.z, h.z, a);
                a = fmaf(w.w, h.w, a);
                a8[mm] = a;
            }
        }
        float bts = b_ts[jh];
#pragma unroll
        for (int mm = 0; mm < 8; ++mm) {
            int m = mg * 8 + mm;
            sXcat[m * 256 + HID + jh] = fmaxf(a8[mm] + bts, 0.0f);
        }
    }
    __syncthreads();

    // c1 = relu(xcat @ W_c1^T + b_c1)
    {
        float a8[8] = {0,0,0,0,0,0,0,0};
#pragma unroll 1
        for (int half = 0; half < 2; ++half) {
            __syncthreads();
#pragma unroll
            for (int q = 0; q < 8; ++q) {
                int idx = q * NTHREADS + tid;
                int r = idx >> 5, cc = idx & 31;
                *(float4*)(sWts + r * 132 + cc * 4) =
                    *(const float4*)(W_c1 + r * 256 + half * 128 + cc * 4);
            }
            __syncthreads();
#pragma unroll 1
            for (int k4 = 0; k4 < 32; ++k4) {
                float4 w = *(const float4*)(sWts + jh * 132 + k4 * 4);
#pragma unroll
                for (int mm = 0; mm < 8; ++mm) {
                    int m = mg * 8 + mm;
                    float4 x = *(const float4*)(sXcat + m * 256 + half * 128 + k4 * 4);
                    float a = a8[mm];
                    a = fmaf(w.x, x.x, a);
                    a = fmaf(w.y, x.y, a);
                    a = fmaf(w.z, x.z, a);
                    a = fmaf(w.w, x.w, a);
                    a8[mm] = a;
                }
            }
        }
        float bc1 = b_c1[jh];
#pragma unroll
        for (int mm = 0; mm < 8; ++mm) {
            int m = mg * 8 + mm;
            sC1o[m * 132 + jh] = fmaxf(a8[mm] + bc1, 0.0f);
        }
    }
    __syncthreads();

    if (tid < M_TILE * NACT) {
        int m = tid / NACT, o = tid - m * NACT;
        float a = b_c2[o];
#pragma unroll 1
        for (int k4 = 0; k4 < 32; ++k4) {
            float4 w = *(const float4*)(sWc2 + o * 132 + k4 * 4);
            float4 x = *(const float4*)(sC1o + m * 132 + k4 * 4);
            a = fmaf(w.x, x.x, a);
            a = fmaf(w.y, x.y, a);
            a = fmaf(w.z, x.z, a);
            a = fmaf(w.w, x.w, a);
        }
        out[sSamp[m] * NACT + o] = a;
    }
}

// ---------------- launch ----------------
extern "C" void kernel_launch(void* const* d_in, const int* in_sizes, int n_in,
                              void* d_out, int out_size) {
    const float* s    = (const float*)d_in[0];
    const float* W_os = (const float*)d_in[1];
    const float* b_os = (const float*)d_in[2];
    const float* W_ih = (const float*)d_in[3];
    const float* W_hh = (const float*)d_in[4];
    const float* b_ih = (const float*)d_in[5];
    const float* b_hh = (const float*)d_in[6];
    const float* W_ts = (const float*)d_in[7];
    const float* b_ts = (const float*)d_in[8];
    const float* W_c1 = (const float*)d_in[9];
    const float* b_c1 = (const float*)d_in[10];
    const float* W_c2 = (const float*)d_in[11];
    const float* b_c2 = (const float*)d_in[12];
    float* out = (float*)d_out;

    cudaFuncSetAttribute(k_main, cudaFuncAttributeMaxDynamicSharedMemorySize, SMEM_BYTES);

    k_count<<<B_TOT / 256, 256>>>(s);
    k_prefix<<<1, 1>>>();
    k_scatter<<<B_TOT / 256, 256>>>();
    k_main<<<NCTA, NTHREADS, SMEM_BYTES>>>(s, W_os, b_os, W_ih, W_hh, b_ih, b_hh,
                                           W_ts, b_ts, W_c1, b_c1, W_c2, b_c2, out);
}